// round 16
// baseline (speedup 1.0000x reference)
#include <cuda_runtime.h>
#include <cuda_fp16.h>
#include <math.h>
#include <math_constants.h>
#include <cstdint>

// ---------------- problem constants ----------------
#define H_     16
#define NOPE_  128
#define ROPE_  64
#define VD_    128
#define KVR_   512
#define QKD_   192        // NOPE+ROPE
#define B_     2
#define T_     2048
#define D_     2048
#define BT_    (B_*T_)    // 4096
#define NQA_   (H_*QKD_ + KVR_ + ROPE_)   // 3648 combined q|kvc width
#define GEMM_GRID 296     // persistent: 2 CTAs/SM x 148 SMs

// ---------------- scratch (device globals; no cudaMalloc allowed) ----------------
__device__ float g_qkv[(size_t)BT_ * NQA_];               // [BT, 3648]: q(3072) | kvc(576)
__device__ float g_kvfull[(size_t)BT_ * H_ * (NOPE_+VD_)];
__device__ float g_krope[(size_t)BT_ * ROPE_];

// fp16 operands
__device__ __half g_xh[(size_t)BT_ * D_];
__device__ __half g_lath[(size_t)BT_ * KVR_];
__device__ __half g_yh[(size_t)BT_ * H_ * VD_];
__device__ __half g_wqa_h[(size_t)NQA_ * D_];             // [3648, 2048] = wq^T | wkv_a^T
__device__ __half g_wbt_h[(size_t)(H_*(NOPE_+VD_)) * KVR_];
__device__ __half g_wot_h[(size_t)D_ * (H_*VD_)];

// ---------------- helpers ----------------
__device__ __forceinline__ uint32_t smem_u32(const void* p) {
    uint32_t a;
    asm("{ .reg .u64 t; cvta.to.shared.u64 t, %1; cvt.u32.u64 %0, t; }" : "=r"(a) : "l"(p));
    return a;
}

__device__ __forceinline__ void ldsm_x4(uint32_t* r, uint32_t addr) {
    asm volatile("ldmatrix.sync.aligned.m8n8.x4.shared.b16 {%0,%1,%2,%3}, [%4];"
                 : "=r"(r[0]), "=r"(r[1]), "=r"(r[2]), "=r"(r[3]) : "r"(addr));
}
__device__ __forceinline__ void ldsm_x4_trans(uint32_t* r, uint32_t addr) {
    asm volatile("ldmatrix.sync.aligned.m8n8.x4.trans.shared.b16 {%0,%1,%2,%3}, [%4];"
                 : "=r"(r[0]), "=r"(r[1]), "=r"(r[2]), "=r"(r[3]) : "r"(addr));
}

__device__ __forceinline__ void mma16816h(float* c, const uint32_t* a, const uint32_t* b) {
    asm volatile(
        "mma.sync.aligned.m16n8k16.row.col.f32.f16.f16.f32 "
        "{%0,%1,%2,%3}, {%4,%5,%6,%7}, {%8,%9}, {%0,%1,%2,%3};"
        : "+f"(c[0]), "+f"(c[1]), "+f"(c[2]), "+f"(c[3])
        : "r"(a[0]), "r"(a[1]), "r"(a[2]), "r"(a[3]), "r"(b[0]), "r"(b[1]));
}

__device__ __forceinline__ uint32_t pack_f16x2(float lo, float hi) {
    uint32_t d;
    asm("cvt.rn.f16x2.f32 %0, %1, %2;" : "=r"(d) : "f"(hi), "f"(lo));
    return d;
}

__device__ __forceinline__ void cvt_store8(uint32_t addr, float4 v) {
    uint32_t p0 = pack_f16x2(v.x, v.y);
    uint32_t p1 = pack_f16x2(v.z, v.w);
    asm volatile("st.shared.v2.b32 [%0], {%1,%2};" :: "r"(addr), "r"(p0), "r"(p1) : "memory");
}

__device__ __forceinline__ void cp16(uint32_t dst, const void* src, bool pred) {
    int sz = pred ? 16 : 0;
    asm volatile("cp.async.cg.shared.global [%0], [%1], 16, %2;"
                 :: "r"(dst), "l"(src), "r"(sz) : "memory");
}
#define CP_COMMIT() asm volatile("cp.async.commit_group;" ::: "memory")
#define CP_WAIT0()  asm volatile("cp.async.wait_group 0;" ::: "memory")

// ---------------- persistent fp16 HMMA GEMM, K-chunk 64, 2-stage, 2 CTAs/SM ----------------
#define GT_PITCHB 144
#define GT_TILE   18432
#define GT_BUF    36864
#define GM_SMEM   (2 * GT_BUF)   // 72 KB

__device__ __forceinline__ void gemm_cp_chunk(
    uint32_t sbase, const __half* A, const __half* Bm,
    int bm0, int bn0, int K, int Nn, int k0, int tid)
{
#pragma unroll
    for (int l = 0; l < 8; l++) {
        const int u = l * 256 + tid;      // 0..2047
        const int tile = u >> 10;         // 0..1
        const int r = (u >> 3) & 127;
        const int c4 = u & 7;             // 8 x 16B = 128B row
        const uint32_t dst = sbase + tile * GT_TILE + r * GT_PITCHB + c4 * 16;
        const __half* src;
        int row;
        bool ok = true;
        if (tile == 0) { src = A; row = bm0 + r; }
        else {
            src = Bm;
            row = bn0 + r;
            ok = (row < Nn);
            if (!ok) row = Nn - 1;
        }
        cp16(dst, src + (size_t)row * K + k0 + c4 * 8, ok);
    }
}

__device__ __forceinline__ void gemm_compute(
    uint32_t sbase, int wm, int wn, int lane, float c[4][4][4])
{
#pragma unroll
    for (int ks = 0; ks < 64; ks += 16) {
        uint32_t Bhf[4][2];
#pragma unroll
        for (int nj = 0; nj < 2; nj++) {
            const int nrow = wn * 32 + nj * 16 + ((lane >> 4) & 1) * 8 + (lane & 7);
            const uint32_t b = sbase + GT_TILE + nrow * GT_PITCHB
                             + (ks + ((lane >> 3) & 1) * 8) * 2;
            ldsm_x4(&Bhf[nj * 2][0], b);
        }
#pragma unroll
        for (int mi = 0; mi < 4; mi++) {
            uint32_t ah[4];
            const int row = wm * 64 + mi * 16 + (lane & 15);
            const uint32_t a = sbase + row * GT_PITCHB + (ks + (lane >> 4) * 8) * 2;
            ldsm_x4(ah, a);
#pragma unroll
            for (int ni = 0; ni < 4; ni++)
                mma16816h(c[mi][ni], ah, Bhf[ni]);
        }
    }
}

__global__ void __launch_bounds__(256, 2) gemm_mma(
    const __half* __restrict__ A, const __half* __restrict__ Bm,
    float* __restrict__ C, int M, int Nn, int K)
{
    extern __shared__ char smem[];
    const uint32_t sb = smem_u32(smem);
    const int tid = threadIdx.x;
    const int lane = tid & 31;
    const int wid = tid >> 5;
    const int wm = wid & 1;
    const int wn = wid >> 1;

    const int ntn = (Nn + 127) >> 7;
    const int ntiles = ntn * (M >> 7);
    const int nc = K >> 6;   // chunks of 64 (always even here)

    for (int tIdx = blockIdx.x; tIdx < ntiles; tIdx += gridDim.x) {
        const int bn0 = (tIdx % ntn) * 128;
        const int bm0 = (tIdx / ntn) * 128;

        float c[4][4][4];
#pragma unroll
        for (int mi = 0; mi < 4; mi++)
#pragma unroll
            for (int ni = 0; ni < 4; ni++)
#pragma unroll
                for (int k = 0; k < 4; k++) c[mi][ni][k] = 0.f;

        gemm_cp_chunk(sb, A, Bm, bm0, bn0, K, Nn, 0, tid);
        CP_COMMIT();

        for (int i = 0; i < nc; i++) {
            CP_WAIT0();
            __syncthreads();
            if (i + 1 < nc) {
                gemm_cp_chunk(sb + ((i + 1) & 1) * GT_BUF, A, Bm,
                              bm0, bn0, K, Nn, (i + 1) * 64, tid);
                CP_COMMIT();
            }
            gemm_compute(sb + (i & 1) * GT_BUF, wm, wn, lane, c);
        }

        const int g = lane >> 2;
        const int t = lane & 3;
#pragma unroll
        for (int mi = 0; mi < 4; mi++) {
            const int row = bm0 + wm * 64 + mi * 16 + g;
#pragma unroll
            for (int ni = 0; ni < 4; ni++) {
                const int col = bn0 + wn * 32 + ni * 8 + 2 * t;
                if (col < Nn) {
                    float2 v0 = make_float2(c[mi][ni][0], c[mi][ni][1]);
                    float2 v1 = make_float2(c[mi][ni][2], c[mi][ni][3]);
                    *(float2*)&C[(size_t)row * Nn + col] = v0;
                    *(float2*)&C[(size_t)(row + 8) * Nn + col] = v1;
                }
            }
        }
        // next tile's prologue writes buf0; stragglers only touch buf (nc-1)&1 = 1 -> safe
    }
}

// ---------------- fp32 -> fp16 convert ----------------
__global__ __launch_bounds__(256) void convert_kernel(
    const float* __restrict__ x, __half* __restrict__ h, int n4)
{
    int i = blockIdx.x * 256 + threadIdx.x;
    if (i >= n4) return;
    float4 v = ((const float4*)x)[i];
    ((__half2*)h)[i*2]   = __halves2half2(__float2half_rn(v.x), __float2half_rn(v.y));
    ((__half2*)h)[i*2+1] = __halves2half2(__float2half_rn(v.z), __float2half_rn(v.w));
}

// ---------------- transpose + fp16 convert: W[K,N] fp32 -> Wt [N,K] fp16 ----------------
__global__ __launch_bounds__(256) void transpose_split_kernel(
    const float* __restrict__ W, __half* __restrict__ th, int K, int N)
{
    __shared__ float tile[32][33];
    const int bx = blockIdx.x * 32;
    const int by = blockIdx.y * 32;
    const int txi = threadIdx.x & 31;
    const int tyi = threadIdx.x >> 5;
#pragma unroll
    for (int j = 0; j < 32; j += 8) {
        int kk = by + tyi + j, nn = bx + txi;
        if (kk < K && nn < N) tile[tyi + j][txi] = W[(size_t)kk * N + nn];
    }
    __syncthreads();
#pragma unroll
    for (int j = 0; j < 32; j += 8) {
        int nn = bx + tyi + j, kk = by + txi;
        if (nn < N && kk < K)
            th[(size_t)nn * K + kk] = __float2half_rn(tile[txi][tyi + j]);
    }
}

// ---------------- RMSNorm: qkv[:, 3072:3584] -> lath fp16 ----------------
__global__ __launch_bounds__(256) void rmsnorm_kernel(
    const float* __restrict__ qkv, const float* __restrict__ w,
    __half* __restrict__ lath)
{
    const int row = blockIdx.x;
    const float* x = qkv + (size_t)row * NQA_ + H_ * QKD_;
    const int tid = threadIdx.x;

    float v0 = x[tid];
    float v1 = x[tid + 256];
    float ss = v0 * v0 + v1 * v1;
#pragma unroll
    for (int off = 16; off; off >>= 1)
        ss += __shfl_xor_sync(0xffffffffu, ss, off);

    __shared__ float red[8];
    if ((tid & 31) == 0) red[tid >> 5] = ss;
    __syncthreads();
    float tot = 0.f;
#pragma unroll
    for (int i = 0; i < 8; i++) tot += red[i];

    float nrm = rsqrtf(tot * (1.f / 512.f) + 1e-6f);
    __half* o = lath + (size_t)row * KVR_;
    o[tid]       = __float2half_rn(v0 * nrm * w[tid]);
    o[tid + 256] = __float2half_rn(v1 * nrm * w[tid + 256]);
}

// ---------------- RoPE on qkv ----------------
__global__ __launch_bounds__(256) void rope_q_kernel(float* __restrict__ qkv)
{
    int idx = blockIdx.x * 256 + threadIdx.x;
    if (idx >= BT_ * H_ * 32) return;
    int i  = idx & 31;
    int h  = (idx >> 5) & (H_ - 1);
    int bt = idx >> 9;
    int t  = bt & (T_ - 1);

    float inv = powf(10000.f, -(float)(2 * i) / 64.f);
    float f = (float)t * inv;
    float c = cosf(f), s = sinf(f);

    float* p = qkv + (size_t)bt * NQA_ + h * QKD_ + NOPE_;
    float x1 = p[i], x2 = p[i + 32];
    p[i]      = x1 * c - x2 * s;
    p[i + 32] = x2 * c + x1 * s;
}

__global__ __launch_bounds__(256) void rope_k_kernel(
    const float* __restrict__ qkv, float* __restrict__ krope)
{
    int idx = blockIdx.x * 256 + threadIdx.x;
    if (idx >= BT_ * 32) return;
    int i  = idx & 31;
    int bt = idx >> 5;
    int t  = bt & (T_ - 1);

    float inv = powf(10000.f, -(float)(2 * i) / 64.f);
    float f = (float)t * inv;
    float c = cosf(f), s = sinf(f);

    const float* p = qkv + (size_t)bt * NQA_ + H_ * QKD_ + KVR_;
    float x1 = p[i], x2 = p[i + 32];
    float* o = krope + (size_t)bt * ROPE_;
    o[i]      = x1 * c - x2 * s;
    o[i + 32] = x2 * c + x1 * s;
}

// ---------------- fp16 HMMA causal flash attention (single product) ----------------
#define ABQ 128
#define ABK 64
#define AQ_PITCH 400
#define AK_PITCH 400
#define AV_PITCH 272
#define OFF_Q 0
#define OFF_K 51200
#define OFF_V 76800
#define ATTN_SMEM 94208

__device__ __forceinline__ float quadmax(float v) {
    v = fmaxf(v, __shfl_xor_sync(0xffffffffu, v, 1));
    v = fmaxf(v, __shfl_xor_sync(0xffffffffu, v, 2));
    return v;
}
__device__ __forceinline__ float quadsum(float v) {
    v += __shfl_xor_sync(0xffffffffu, v, 1);
    v += __shfl_xor_sync(0xffffffffu, v, 2);
    return v;
}

__global__ __launch_bounds__(256) void attn_mma_kernel(
    const float* __restrict__ qkv, const float* __restrict__ kvfull,
    const float* __restrict__ krope, __half* __restrict__ yh)
{
    extern __shared__ char smem[];
    const uint32_t sb = smem_u32(smem);
    const int b  = blockIdx.z;
    const int h  = blockIdx.y;
    const int qt = gridDim.x - 1 - blockIdx.x;   // heavy tiles scheduled first
    const int q0 = qt * ABQ;
    const int tid = threadIdx.x;
    const int lane = tid & 31;
    const int w = tid >> 5;
    const int g = lane >> 2;
    const int t = lane & 3;
    const float scale = 0.07216878364870322f;

    // load Q tile [128][192] fp32 (from combined qkv, stride NQA_) -> fp16 smem
#pragma unroll
    for (int l = 0; l < 24; l++) {
        int u = l * 256 + tid;
        int row = u / 48, c4 = u % 48, d = c4 * 4;
        float4 v = *(const float4*)&qkv[(size_t)(b * T_ + q0 + row) * NQA_ + h * QKD_ + d];
        cvt_store8(sb + OFF_Q + row * AQ_PITCH + d * 2, v);
    }

    float oc[16][4];
#pragma unroll
    for (int d = 0; d < 16; d++) { oc[d][0]=0.f; oc[d][1]=0.f; oc[d][2]=0.f; oc[d][3]=0.f; }
    float m0 = -CUDART_INF_F, m1 = -CUDART_INF_F, l0s = 0.f, l1s = 0.f;

    const int row0 = q0 + w * 16 + g;
    const int wrow_max = q0 + w * 16 + 15;

    const int nkt = 2 * qt + 2;
    for (int kt = 0; kt < nkt; kt++) {
        const int k0 = kt * ABK;
        __syncthreads();

#pragma unroll
        for (int l = 0; l < 12; l++) {
            int u = l * 256 + tid;
            int row = u / 48, c4 = u % 48, d = c4 * 4;
            size_t tok = (size_t)(b * T_ + k0 + row);
            float4 v;
            if (d < NOPE_) v = *(const float4*)&kvfull[(tok * H_ + h) * (NOPE_+VD_) + d];
            else           v = *(const float4*)&krope[tok * ROPE_ + (d - NOPE_)];
            cvt_store8(sb + OFF_K + row * AK_PITCH + d * 2, v);
        }
#pragma unroll
        for (int l = 0; l < 8; l++) {
            int u = l * 256 + tid;
            int row = u >> 5, c4 = u & 31, d = c4 * 4;
            size_t tok = (size_t)(b * T_ + k0 + row);
            float4 v = *(const float4*)&kvfull[(tok * H_ + h) * (NOPE_+VD_) + NOPE_ + d];
            cvt_store8(sb + OFF_V + row * AV_PITCH + d * 2, v);
        }
        __syncthreads();

        if (k0 > wrow_max) continue;

        float sc[8][4];
#pragma unroll
        for (int j = 0; j < 8; j++) { sc[j][0]=0.f; sc[j][1]=0.f; sc[j][2]=0.f; sc[j][3]=0.f; }

#pragma unroll
        for (int kb = 0; kb < 12; kb++) {
            uint32_t qa = sb + OFF_Q + (w * 16 + (lane & 15)) * AQ_PITCH
                        + (kb * 16 + (lane >> 4) * 8) * 2;
            uint32_t aq[4];
            ldsm_x4(aq, qa);
            uint32_t kh[8][2];
#pragma unroll
            for (int nj = 0; nj < 4; nj++) {
                uint32_t ka = sb + OFF_K
                            + (nj * 16 + ((lane >> 4) & 1) * 8 + (lane & 7)) * AK_PITCH
                            + (kb * 16 + ((lane >> 3) & 1) * 8) * 2;
                ldsm_x4(&kh[nj * 2][0], ka);
            }
#pragma unroll
            for (int j = 0; j < 8; j++)
                mma16816h(sc[j], aq, kh[j]);
        }

        const bool need_mask = (k0 + ABK - 1 > q0 + w * 16);
#pragma unroll
        for (int j = 0; j < 8; j++) {
            int cbase = k0 + 8 * j + 2 * t;
#pragma unroll
            for (int e = 0; e < 4; e++) {
                int col = cbase + (e & 1);
                int row = (e < 2) ? row0 : row0 + 8;
                float v = sc[j][e] * scale;
                sc[j][e] = (need_mask && col > row) ? -CUDART_INF_F : v;
            }
        }

        float tm0 = -CUDART_INF_F, tm1 = -CUDART_INF_F;
#pragma unroll
        for (int j = 0; j < 8; j++) {
            tm0 = fmaxf(tm0, fmaxf(sc[j][0], sc[j][1]));
            tm1 = fmaxf(tm1, fmaxf(sc[j][2], sc[j][3]));
        }
        tm0 = quadmax(tm0); tm1 = quadmax(tm1);
        float mn0 = fmaxf(m0, tm0), mn1 = fmaxf(m1, tm1);
        float corr0 = __expf(m0 - mn0), corr1 = __expf(m1 - mn1);
        float rs0 = 0.f, rs1 = 0.f;
#pragma unroll
        for (int j = 0; j < 8; j++) {
            sc[j][0] = __expf(sc[j][0] - mn0);
            sc[j][1] = __expf(sc[j][1] - mn0);
            sc[j][2] = __expf(sc[j][2] - mn1);
            sc[j][3] = __expf(sc[j][3] - mn1);
            rs0 += sc[j][0] + sc[j][1];
            rs1 += sc[j][2] + sc[j][3];
        }
        rs0 = quadsum(rs0); rs1 = quadsum(rs1);
        l0s = l0s * corr0 + rs0;
        l1s = l1s * corr1 + rs1;
        m0 = mn0; m1 = mn1;
#pragma unroll
        for (int d = 0; d < 16; d++) {
            oc[d][0] *= corr0; oc[d][1] *= corr0;
            oc[d][2] *= corr1; oc[d][3] *= corr1;
        }

#pragma unroll
        for (int kb2 = 0; kb2 < 4; kb2++) {
            uint32_t pa[4];
#pragma unroll
            for (int half = 0; half < 2; half++) {
                int j = 2 * kb2 + half;
                pa[half * 2 + 0] = pack_f16x2(sc[j][0], sc[j][1]);
                pa[half * 2 + 1] = pack_f16x2(sc[j][2], sc[j][3]);
            }
#pragma unroll
            for (int dp = 0; dp < 8; dp++) {
                uint32_t vh[4];
                uint32_t va = sb + OFF_V
                            + (kb2 * 16 + (lane & 7) + ((lane >> 3) & 1) * 8) * AV_PITCH
                            + (dp * 16 + (lane >> 4) * 8) * 2;
                ldsm_x4_trans(vh, va);
                mma16816h(oc[dp * 2],     pa, &vh[0]);
                mma16816h(oc[dp * 2 + 1], pa, &vh[2]);
            }
        }
    }

    // ---- epilogue: write fp16 yh directly ----
    float inv0 = 1.f / l0s, inv1 = 1.f / l1s;
#pragma unroll
    for (int d = 0; d < 16; d++) {
        int col = d * 8 + 2 * t;
        size_t base0 = (((size_t)(b * T_ + row0)) * H_ + h) * VD_ + col;
        size_t base1 = (((size_t)(b * T_ + row0 + 8)) * H_ + h) * VD_ + col;
        *(uint32_t*)&yh[base0] = pack_f16x2(oc[d][0] * inv0, oc[d][1] * inv0);
        *(uint32_t*)&yh[base1] = pack_f16x2(oc[d][2] * inv1, oc[d][3] * inv1);
    }
}

// ---------------- launch ----------------
extern "C" void kernel_launch(void* const* d_in, const int* in_sizes, int n_in,
                              void* d_out, int out_size)
{
    const float* x      = (const float*)d_in[0];
    const float* wq     = (const float*)d_in[1];
    const float* wkv_a  = (const float*)d_in[2];
    const float* wkv_b  = (const float*)d_in[3];
    const float* wo     = (const float*)d_in[4];
    const float* kvw    = (const float*)d_in[5];
    float* out = (float*)d_out;

    float *qkvp, *kvfp, *krp;
    cudaGetSymbolAddress((void**)&qkvp, g_qkv);
    cudaGetSymbolAddress((void**)&kvfp, g_kvfull);
    cudaGetSymbolAddress((void**)&krp,  g_krope);

    __half *xh, *lath, *yh, *wqah, *wbth, *woth;
    cudaGetSymbolAddress((void**)&xh,   g_xh);
    cudaGetSymbolAddress((void**)&lath, g_lath);
    cudaGetSymbolAddress((void**)&yh,   g_yh);
    cudaGetSymbolAddress((void**)&wqah, g_wqa_h);
    cudaGetSymbolAddress((void**)&wbth, g_wbt_h);
    cudaGetSymbolAddress((void**)&woth, g_wot_h);

    cudaFuncSetAttribute(gemm_mma, cudaFuncAttributeMaxDynamicSharedMemorySize, GM_SMEM);
    cudaFuncSetAttribute(attn_mma_kernel, cudaFuncAttributeMaxDynamicSharedMemorySize, ATTN_SMEM);

    // ---- prep ----
    convert_kernel<<<(BT_*D_/4 + 255)/256, 256>>>(x, xh, BT_*D_/4);
    transpose_split_kernel<<<dim3((H_*QKD_)/32, D_/32), 256>>>(wq, wqah, D_, H_*QKD_);
    transpose_split_kernel<<<dim3((KVR_+ROPE_)/32, D_/32), 256>>>(
        wkv_a, wqah + (size_t)(H_*QKD_) * D_, D_, KVR_+ROPE_);
    transpose_split_kernel<<<dim3((H_*(NOPE_+VD_))/32, KVR_/32), 256>>>(wkv_b, wbth, KVR_, H_*(NOPE_+VD_));
    transpose_split_kernel<<<dim3(D_/32, (H_*VD_)/32), 256>>>(wo, woth, H_*VD_, D_);

    // ---- merged q|kvc = x @ [wq | wkv_a] : [4096, 3648] (persistent grid) ----
    gemm_mma<<<GEMM_GRID, 256, GM_SMEM>>>(xh, wqah, qkvp, BT_, NQA_, D_);
    // ---- rmsnorm (-> fp16 lath) + rope ----
    rmsnorm_kernel<<<BT_, 256>>>(qkvp, kvw, lath);
    rope_q_kernel<<<(BT_*H_*32)/256, 256>>>(qkvp);
    rope_k_kernel<<<(BT_*32)/256, 256>>>(qkvp, krp);
    // ---- kv_full = lat @ wkv_b ----
    gemm_mma<<<GEMM_GRID, 256, GM_SMEM>>>(lath, wbth, kvfp, BT_, H_*(NOPE_+VD_), KVR_);
    // ---- attention (heavy tiles first, writes fp16 yh directly) ----
    attn_mma_kernel<<<dim3(T_/ABQ, H_, B_), 256, ATTN_SMEM>>>(qkvp, kvfp, krp, yh);
    // ---- out = y @ wo ----
    gemm_mma<<<GEMM_GRID, 256, GM_SMEM>>>(yh, woth, out, BT_, D_, H_*VD_);
}